// round 7
// baseline (speedup 1.0000x reference)
#include <cuda_runtime.h>
#include <cuda_bf16.h>

#define N_ROWS 8192
#define F_DIM  512
#define K_KEEP 4096

// Scratch (device globals — no allocation allowed)
__device__ __align__(16) float g_y[N_ROWS];
__device__ float g_inv_norm;
__device__ __align__(16) int   g_idx[K_KEEP];

// ---------------------------------------------------------------------------
// Kernel A: y = X @ kernel. One warp per 2 rows (8 independent float4 loads
// in flight per thread for MLP). grid = 512, block = 256.
// ---------------------------------------------------------------------------
__global__ __launch_bounds__(256) void compute_y_kernel(
    const float* __restrict__ X, const float* __restrict__ kern)
{
    int warp = threadIdx.x >> 5;
    int lane = threadIdx.x & 31;
    int gw   = blockIdx.x * 8 + warp;       // 4096 warps
    int r    = gw * 2;

    const float4* k4 = (const float4*)kern;
    const float4* xa = (const float4*)(X + (size_t)r * F_DIM);
    const float4* xb = (const float4*)(X + (size_t)(r + 1) * F_DIM);
    float4 va[4], vb[4], kc[4];
#pragma unroll
    for (int it = 0; it < 4; it++) va[it] = xa[lane + 32 * it];
#pragma unroll
    for (int it = 0; it < 4; it++) vb[it] = xb[lane + 32 * it];
#pragma unroll
    for (int it = 0; it < 4; it++) kc[it] = __ldg(&k4[lane + 32 * it]);

    float aa = 0.f, ab = 0.f;
#pragma unroll
    for (int it = 0; it < 4; it++) {
        aa = fmaf(va[it].x, kc[it].x, aa);
        aa = fmaf(va[it].y, kc[it].y, aa);
        aa = fmaf(va[it].z, kc[it].z, aa);
        aa = fmaf(va[it].w, kc[it].w, aa);
        ab = fmaf(vb[it].x, kc[it].x, ab);
        ab = fmaf(vb[it].y, kc[it].y, ab);
        ab = fmaf(vb[it].z, kc[it].z, ab);
        ab = fmaf(vb[it].w, kc[it].w, ab);
    }
#pragma unroll
    for (int o = 16; o > 0; o >>= 1) {
        aa += __shfl_xor_sync(0xFFFFFFFFu, aa, o);
        ab += __shfl_xor_sync(0xFFFFFFFFu, ab, o);
    }
    if (lane == 0) { g_y[r] = aa; g_y[r + 1] = ab; }
}

// ---------------------------------------------------------------------------
// Block scans (1024 threads, 32 warps)
// ---------------------------------------------------------------------------
__device__ __forceinline__ int block_exscan(int v, int* s_warp)
{
    __syncthreads();
    int lane = threadIdx.x & 31, warp = threadIdx.x >> 5;
    int incl = v;
#pragma unroll
    for (int o = 1; o < 32; o <<= 1) {
        int t = __shfl_up_sync(0xFFFFFFFFu, incl, o);
        if (lane >= o) incl += t;
    }
    if (lane == 31) s_warp[warp] = incl;
    __syncthreads();
    if (warp == 0) {
        int w  = s_warp[lane];
        int wi = w;
#pragma unroll
        for (int o = 1; o < 32; o <<= 1) {
            int t = __shfl_up_sync(0xFFFFFFFFu, wi, o);
            if (lane >= o) wi += t;
        }
        s_warp[lane] = wi - w;
    }
    __syncthreads();
    return s_warp[warp] + incl - v;
}

__device__ __forceinline__ int block_exscan_tot(int v, int* s_warp, int* s_tot)
{
    __syncthreads();
    int lane = threadIdx.x & 31, warp = threadIdx.x >> 5;
    int incl = v;
#pragma unroll
    for (int o = 1; o < 32; o <<= 1) {
        int t = __shfl_up_sync(0xFFFFFFFFu, incl, o);
        if (lane >= o) incl += t;
    }
    if (lane == 31) s_warp[warp] = incl;
    __syncthreads();
    if (warp == 0) {
        int w  = s_warp[lane];
        int wi = w;
#pragma unroll
        for (int o = 1; o < 32; o <<= 1) {
            int t = __shfl_up_sync(0xFFFFFFFFu, wi, o);
            if (lane >= o) wi += t;
        }
        if (lane == 31) *s_tot = wi;
        s_warp[lane] = wi - w;
    }
    __syncthreads();
    return s_warp[warp] + incl - v;
}

// ---------------------------------------------------------------------------
// Kernel B: single block, 1024 threads. Radix-select exact K-th largest key,
// emit idx[] ascending, compute inv_norm.  (round-2 proven version)
// ---------------------------------------------------------------------------
__global__ __launch_bounds__(1024) void select_kernel(const float* __restrict__ kern)
{
    __shared__ int h[2048];
    __shared__ int s_warp[32];
    __shared__ int s_tot;
    __shared__ float s_red[32];
    __shared__ unsigned s_B;
    __shared__ int s_after;

    int tid  = threadIdx.x;
    int lane = tid & 31, warp = tid >> 5;

    const float4* y4 = (const float4*)g_y;
    float4 a = y4[tid * 2 + 0];
    float4 b = y4[tid * 2 + 1];
    float v[8] = {a.x, a.y, a.z, a.w, b.x, b.y, b.z, b.w};
    unsigned key[8];
#pragma unroll
    for (int j = 0; j < 8; j++) {
        unsigned u = __float_as_uint(v[j]);
        key[j] = (u & 0x80000000u) ? ~u : (u | 0x80000000u);
    }

    float s = 0.f;
    if (tid < F_DIM) { float kv = kern[tid]; s = kv * kv; }
#pragma unroll
    for (int o = 16; o > 0; o >>= 1) s += __shfl_xor_sync(0xFFFFFFFFu, s, o);
    if (lane == 0) s_red[warp] = s;
    __syncthreads();
    if (warp == 0) {
        float t = s_red[lane];
#pragma unroll
        for (int o = 16; o > 0; o >>= 1) t += __shfl_xor_sync(0xFFFFFFFFu, t, o);
        if (lane == 0) s_red[0] = rsqrtf(t);
    }
    __syncthreads();
    float inv_norm = s_red[0];

    const int shifts[3] = {21, 10, 0};
    const int nbv[3]    = {2048, 2048, 1024};
    unsigned prefix = 0, maskdone = 0;
    int krem = K_KEEP;

#pragma unroll 1
    for (int p = 0; p < 3; p++) {
        int nb = nbv[p];
        int shift = shifts[p];
        unsigned bmask = (unsigned)(nb - 1);
        h[tid] = 0; h[tid + 1024] = 0;
        __syncthreads();
#pragma unroll
        for (int j = 0; j < 8; j++)
            if ((key[j] & maskdone) == prefix)
                atomicAdd(&h[(key[j] >> shift) & bmask], 1);
        __syncthreads();

        if (nb == 2048) {
            int v0 = h[2 * tid], v1 = h[2 * tid + 1];
            int tsum = v0 + v1;
            int ex = block_exscan_tot(tsum, s_warp, &s_tot);
            int total = s_tot;
            int suf0 = total - ex;
            int suf1 = suf0 - v0;
            int suf2 = suf1 - v1;
            if (suf0 >= krem && suf1 < krem) { s_B = 2u*tid + 0; s_after = suf1; }
            if (suf1 >= krem && suf2 < krem) { s_B = 2u*tid + 1; s_after = suf2; }
        } else {
            int v0 = (tid < 1024) ? h[tid] : 0;
            int ex = block_exscan_tot(v0, s_warp, &s_tot);
            int total = s_tot;
            int suf0 = total - ex;
            int suf1 = suf0 - v0;
            if (suf0 >= krem && suf1 < krem) { s_B = (unsigned)tid; s_after = suf1; }
        }
        __syncthreads();
        prefix   |= s_B << shift;
        maskdone |= bmask << shift;
        krem     -= s_after;
        __syncthreads();
    }

    unsigned T = prefix;
    int tie_keep = krem;

    int myeq = 0;
#pragma unroll
    for (int j = 0; j < 8; j++) myeq += (key[j] == T);
    int eq_before = block_exscan(myeq, s_warp);

    bool keep[8];
    int e = eq_before, mykeep = 0;
#pragma unroll
    for (int j = 0; j < 8; j++) {
        if (key[j] == T) { keep[j] = (e < tie_keep); e++; }
        else             { keep[j] = (key[j] > T); }
        mykeep += keep[j];
    }
    int pos = block_exscan(mykeep, s_warp);
#pragma unroll
    for (int j = 0; j < 8; j++)
        if (keep[j]) g_idx[pos++] = tid * 8 + j;

    if (tid == 0) g_inv_norm = inv_norm;
}

// ---------------------------------------------------------------------------
// Kernel C: fused gather, 256 threads/block.
//   blocks [0, 4096):       A_pooled — stage full 32KB A-row in SMEM
//                           (coalesced), then gather columns from SMEM.
//   blocks [4096, 6144):    X_pooled — 2 rows per block, tanh gating.
// ---------------------------------------------------------------------------
__global__ __launch_bounds__(256) void gather_kernel(
    const float* __restrict__ X, const float* __restrict__ A,
    float* __restrict__ out)
{
    __shared__ float srow[N_ROWS];              // 32 KB
    int bid = blockIdx.x;
    int tid = threadIdx.x;

    if (bid < K_KEEP) {
        int r = bid;
        const float4* rowp = (const float4*)(A + (size_t)g_idx[r] * N_ROWS);
        float4* s4 = (float4*)srow;
        // stage: 2048 float4, fully coalesced
#pragma unroll
        for (int it = 0; it < 8; it++) {
            int c = tid + it * 256;
            s4[c] = __ldcs(&rowp[c]);
        }
        __syncthreads();
        // gather selected columns from SMEM, write coalesced
        const int4* idx4 = (const int4*)g_idx;
        float4* o = (float4*)(out + (size_t)K_KEEP * F_DIM + (size_t)r * K_KEEP);
#pragma unroll
        for (int it = 0; it < 4; it++) {
            int c = tid + it * 256;
            int4 i = __ldg(&idx4[c]);
            float4 v;
            v.x = srow[i.x];
            v.y = srow[i.y];
            v.z = srow[i.z];
            v.w = srow[i.w];
            __stcs(&o[c], v);
        }
    } else {
        int r   = (bid - K_KEEP) * 2 + (tid >> 7);
        int t   = tid & 127;
        int row = g_idx[r];
        float gate = tanhf(g_y[row] * g_inv_norm);
        const float4* xr = (const float4*)(X + (size_t)row * F_DIM);
        float4* o = (float4*)(out + (size_t)r * F_DIM);
        float4 x = xr[t];
        o[t] = make_float4(x.x * gate, x.y * gate, x.z * gate, x.w * gate);
    }
}

// ---------------------------------------------------------------------------
extern "C" void kernel_launch(void* const* d_in, const int* in_sizes, int n_in,
                              void* d_out, int out_size)
{
    const float* X    = (const float*)d_in[0];
    const float* A    = (const float*)d_in[1];
    const float* kern = (const float*)d_in[2];
    float* out = (float*)d_out;

    compute_y_kernel<<<512, 256>>>(X, kern);
    select_kernel<<<1, 1024>>>(kern);
    gather_kernel<<<K_KEEP + 2048, 256>>>(X, A, out);
}

// round 9
// speedup vs baseline: 1.0825x; 1.0825x over previous
#include <cuda_runtime.h>
#include <cuda_bf16.h>

#define N_ROWS 8192
#define F_DIM  512
#define K_KEEP 4096
#define NB1    1024       // blocks for kernel 1

// Scratch (device globals — no allocation allowed)
__device__ __align__(16) float    g_y[N_ROWS];
__device__ float                  g_inv_norm;
__device__ __align__(16) int      g_idx[K_KEEP];
__device__ __align__(16) unsigned g_keepw[N_ROWS / 32];  // keep bitmask per 32 cols
__device__ __align__(16) int      g_wpre[N_ROWS / 32];   // kept-count prefix per word
__device__ unsigned g_count = 0;

// ---------------------------------------------------------------------------
// Block scans for 256 threads (8 warps)
// ---------------------------------------------------------------------------
__device__ __forceinline__ int block_exscan8(int v, int* s_warp)
{
    __syncthreads();
    int lane = threadIdx.x & 31, warp = threadIdx.x >> 5;
    int incl = v;
#pragma unroll
    for (int o = 1; o < 32; o <<= 1) {
        int t = __shfl_up_sync(0xFFFFFFFFu, incl, o);
        if (lane >= o) incl += t;
    }
    if (lane == 31) s_warp[warp] = incl;
    __syncthreads();
    if (warp == 0 && lane < 8) {
        int w  = s_warp[lane];
        int wi = w;
#pragma unroll
        for (int o = 1; o < 8; o <<= 1) {
            int t = __shfl_up_sync(0x000000FFu, wi, o);
            if (lane >= o) wi += t;
        }
        s_warp[lane] = wi - w;
    }
    __syncthreads();
    return s_warp[warp] + incl - v;
}

__device__ __forceinline__ int block_exscan8_tot(int v, int* s_warp, int* s_tot)
{
    __syncthreads();
    int lane = threadIdx.x & 31, warp = threadIdx.x >> 5;
    int incl = v;
#pragma unroll
    for (int o = 1; o < 32; o <<= 1) {
        int t = __shfl_up_sync(0xFFFFFFFFu, incl, o);
        if (lane >= o) incl += t;
    }
    if (lane == 31) s_warp[warp] = incl;
    __syncthreads();
    if (warp == 0 && lane < 8) {
        int w  = s_warp[lane];
        int wi = w;
#pragma unroll
        for (int o = 1; o < 8; o <<= 1) {
            int t = __shfl_up_sync(0x000000FFu, wi, o);
            if (lane >= o) wi += t;
        }
        if (lane == 7) *s_tot = wi;
        s_warp[lane] = wi - w;
    }
    __syncthreads();
    return s_warp[warp] + incl - v;
}

// ---------------------------------------------------------------------------
// Kernel 1: compute_y on 1024 blocks (warp per row, round-2 proven config);
// non-zero blocks arrive & exit; block 0 waits, then radix-selects and emits
// g_idx (ascending), g_keepw, g_wpre, g_inv_norm.
// ---------------------------------------------------------------------------
__global__ __launch_bounds__(256) void score_select_kernel(
    const float* __restrict__ X, const float* __restrict__ kern)
{
    __shared__ int h[2048];
    __shared__ int s_warp[8];
    __shared__ int s_tot;
    __shared__ float s_red[8];
    __shared__ unsigned s_B;
    __shared__ int s_after;

    int tid  = threadIdx.x;
    int lane = tid & 31, warp = tid >> 5;
    int bid  = blockIdx.x;

    // -------- Phase 1: y (one warp per row; 8 rows per block) --------------
    {
        int row = bid * 8 + warp;
        const float4* x4 = (const float4*)(X + (size_t)row * F_DIM);
        const float4* k4 = (const float4*)kern;
        float acc = 0.f;
#pragma unroll
        for (int it = 0; it < 4; it++) {
            int j = lane + 32 * it;
            float4 x = x4[j];
            float4 k = __ldg(&k4[j]);
            acc = fmaf(x.x, k.x, acc);
            acc = fmaf(x.y, k.y, acc);
            acc = fmaf(x.z, k.z, acc);
            acc = fmaf(x.w, k.w, acc);
        }
#pragma unroll
        for (int o = 16; o > 0; o >>= 1)
            acc += __shfl_xor_sync(0xFFFFFFFFu, acc, o);
        if (lane == 0) g_y[row] = acc;
    }

    __syncthreads();
    if (bid != 0) {
        if (tid == 0) { __threadfence(); atomicAdd(&g_count, 1); }
        return;
    }

    // -------- Block 0: wait for everyone -----------------------------------
    if (tid == 0) {
        int backoff = 32;
        while (*(volatile unsigned*)&g_count < NB1 - 1) {
            __nanosleep(backoff);
            if (backoff < 256) backoff <<= 1;
        }
        g_count = 0;
        __threadfence();
    }
    __syncthreads();

    // -------- inv_norm (512 elems, 256 threads: 2 each) --------------------
    {
        float k0 = kern[tid], k1 = kern[tid + 256];
        float s = k0 * k0 + k1 * k1;
#pragma unroll
        for (int o = 16; o > 0; o >>= 1) s += __shfl_xor_sync(0xFFFFFFFFu, s, o);
        if (lane == 0) s_red[warp] = s;
        __syncthreads();
        if (warp == 0 && lane < 8) {
            float t = s_red[lane];
#pragma unroll
            for (int o = 4; o > 0; o >>= 1) t += __shfl_xor_sync(0x000000FFu, t, o);
            if (lane == 0) s_red[0] = rsqrtf(t);
        }
        __syncthreads();
        if (tid == 0) g_inv_norm = s_red[0];
    }

    // -------- Radix select: 32 keys/thread (cols tid*32 .. tid*32+31) ------
    const float4* y4 = (const float4*)g_y;
    unsigned key[32];
#pragma unroll
    for (int q = 0; q < 8; q++) {
        float4 a = y4[tid * 8 + q];
        float vv[4] = {a.x, a.y, a.z, a.w};
#pragma unroll
        for (int j = 0; j < 4; j++) {
            unsigned u = __float_as_uint(vv[j]);
            key[q * 4 + j] = (u & 0x80000000u) ? ~u : (u | 0x80000000u);
        }
    }

    const int shifts[3] = {21, 10, 0};
    const int nbv[3]    = {2048, 2048, 1024};
    unsigned prefix = 0, maskdone = 0;
    int krem = K_KEEP;

#pragma unroll 1
    for (int p = 0; p < 3; p++) {
        int nb = nbv[p];
        int shift = shifts[p];
        unsigned bmask = (unsigned)(nb - 1);
#pragma unroll
        for (int q = 0; q < 8; q++) h[tid + q * 256] = 0;
        __syncthreads();
#pragma unroll
        for (int j = 0; j < 32; j++)
            if ((key[j] & maskdone) == prefix)
                atomicAdd(&h[(key[j] >> shift) & bmask], 1);
        __syncthreads();

        if (nb == 2048) {
            int v[8], tsum = 0;
#pragma unroll
            for (int q = 0; q < 8; q++) { v[q] = h[8 * tid + q]; tsum += v[q]; }
            int ex = block_exscan8_tot(tsum, s_warp, &s_tot);
            int suf = s_tot - ex;
#pragma unroll
            for (int q = 0; q < 8; q++) {
                int sn = suf - v[q];
                if (suf >= krem && sn < krem) { s_B = 8u * tid + q; s_after = sn; }
                suf = sn;
            }
        } else {
            int v[4], tsum = 0;
#pragma unroll
            for (int q = 0; q < 4; q++) { v[q] = h[4 * tid + q]; tsum += v[q]; }
            int ex = block_exscan8_tot(tsum, s_warp, &s_tot);
            int suf = s_tot - ex;
#pragma unroll
            for (int q = 0; q < 4; q++) {
                int sn = suf - v[q];
                if (suf >= krem && sn < krem) { s_B = 4u * tid + q; s_after = sn; }
                suf = sn;
            }
        }
        __syncthreads();
        prefix   |= s_B << shift;
        maskdone |= bmask << shift;
        krem     -= s_after;
        __syncthreads();
    }

    unsigned T = prefix;
    int tie_keep = krem;

    int myeq = 0;
#pragma unroll
    for (int j = 0; j < 32; j++) myeq += (key[j] == T);
    int eq_before = block_exscan8(myeq, s_warp);

    unsigned kw = 0;
    int e = eq_before, mykeep = 0;
#pragma unroll
    for (int j = 0; j < 32; j++) {
        bool kp;
        if (key[j] == T) { kp = (e < tie_keep); e++; }
        else             { kp = (key[j] > T); }
        if (kp) { kw |= 1u << j; mykeep++; }
    }
    int pos = block_exscan8(mykeep, s_warp);

    g_keepw[tid] = kw;          // keep bits for cols tid*32..+31
    g_wpre[tid]  = pos;         // kept count before this word
    int pp = pos;
#pragma unroll
    for (int j = 0; j < 32; j++)
        if (kw & (1u << j)) g_idx[pp++] = tid * 32 + j;
}

// ---------------------------------------------------------------------------
// Kernel 2: gather.
//   blocks [0, 4096):     A_pooled — coalesced row read, SMEM-compact, dump.
//   blocks [4096, 6144):  X_pooled — 2 rows per block, tanh gating.
// ---------------------------------------------------------------------------
__global__ __launch_bounds__(256) void gather_kernel(
    const float* __restrict__ X, const float* __restrict__ A,
    float* __restrict__ out)
{
    __shared__ float    sc[K_KEEP];     // 16 KB compact buffer
    __shared__ unsigned skw[256];
    __shared__ int      swp[256];

    int bid = blockIdx.x;
    int tid = threadIdx.x;

    if (bid < K_KEEP) {
        int r = bid;
        skw[tid] = g_keepw[tid];
        swp[tid] = g_wpre[tid];
        const float4* rowp = (const float4*)(A + (size_t)g_idx[r] * N_ROWS);
        __syncthreads();

#pragma unroll
        for (int it = 0; it < 8; it++) {
            int c4 = tid + it * 256;            // float4 index in row
            float4 v = __ldcs(&rowp[c4]);
            int col0 = c4 * 4;
            int w    = col0 >> 5;
            int bo   = col0 & 31;
            unsigned word = skw[w];
            int base = swp[w] + __popc(word & ((1u << bo) - 1u));
            unsigned b = (word >> bo) & 0xFu;
            if (b & 1u) sc[base++] = v.x;
            if (b & 2u) sc[base++] = v.y;
            if (b & 4u) sc[base++] = v.z;
            if (b & 8u) sc[base]   = v.w;
        }
        __syncthreads();

        const float4* s4 = (const float4*)sc;
        float4* o = (float4*)(out + (size_t)K_KEEP * F_DIM + (size_t)r * K_KEEP);
#pragma unroll
        for (int it = 0; it < 4; it++) {
            int c = tid + it * 256;
            __stcs(&o[c], s4[c]);
        }
    } else {
        int r   = (bid - K_KEEP) * 2 + (tid >> 7);
        int t   = tid & 127;
        int row = g_idx[r];
        float gate = tanhf(g_y[row] * g_inv_norm);
        const float4* xr = (const float4*)(X + (size_t)row * F_DIM);
        float4* o = (float4*)(out + (size_t)r * F_DIM);
        float4 x = xr[t];
        o[t] = make_float4(x.x * gate, x.y * gate, x.z * gate, x.w * gate);
    }
}

// ---------------------------------------------------------------------------
extern "C" void kernel_launch(void* const* d_in, const int* in_sizes, int n_in,
                              void* d_out, int out_size)
{
    const float* X    = (const float*)d_in[0];
    const float* A    = (const float*)d_in[1];
    const float* kern = (const float*)d_in[2];
    float* out = (float*)d_out;

    score_select_kernel<<<NB1, 256>>>(X, kern);
    gather_kernel<<<K_KEEP + 2048, 256>>>(X, A, out);
}